// round 2
// baseline (speedup 1.0000x reference)
#include <cuda_runtime.h>
#include <math.h>
#include <stddef.h>

// Problem constants
#define BQ    512   // batch
#define SQ    199   // seq len
#define DQ    512   // hidden dim
#define SKMAX 300
#define TSLOTS 200

// GEMM tiling
#define BM 64
#define BN 64
#define BK 16

// ---------------- scratch (device globals; no runtime allocation) ----------------
__device__ float g_rows[(size_t)BQ * SQ * DQ];   // skill_buf history, [B][S][D]  (~208 MB)
__device__ float g_all [BQ * DQ];                // all_state
__device__ float g_lall[BQ * DQ];                // last_all (gated)
__device__ float g_lsk [BQ * DQ];                // last_sk  (gated)
__device__ float g_h   [BQ * DQ];                // relu hidden
__device__ int   g_lt  [BQ * SKMAX];             // last_time

// precomputed static tables
__device__ float g_pre_gap  [TSLOTS * DQ];  // time_embed @ W_sf_bot + b_sf
__device__ float g_caf      [DQ];           // time_embed[1] @ W_af_bot + b_af
__device__ float g_pre_o1   [SKMAX * DQ];   // skill_embed @ W_o1[2d:3d] + b_o1
__device__ float g_pre_as_sk[SKMAX * DQ];   // skill_embed @ W_as_bot + b_as
__device__ float g_pre_ss_sk[SKMAX * DQ];   // skill_embed @ W_ss_bot + b_ss
__device__ float g_pre_as_an[2 * DQ];       // ans_embed @ W_as_bot
__device__ float g_pre_ss_an[2 * DQ];       // ans_embed @ W_ss_bot

__device__ __forceinline__ float sigf(float z) { return 1.f / (1.f + expf(-z)); }

// ---------------- init ----------------
__global__ void k_init_state(const float* __restrict__ ls_state) {
    int b = blockIdx.x;
    for (int j = threadIdx.x; j < DQ; j += blockDim.x) g_all[b * DQ + j] = ls_state[j];
    for (int k = threadIdx.x; k < SKMAX; k += blockDim.x) g_lt[b * SKMAX + k] = 0;
}

__global__ void k_init_rows(const float* __restrict__ s0) {
    int t = blockIdx.x, b = blockIdx.y;
    size_t o = ((size_t)b * SQ + t) * DQ;
    for (int j = threadIdx.x; j < DQ; j += blockDim.x) g_rows[o + j] = s0[t * DQ + j];
}

// ---------------- precompute static tables (matvec per CTA) ----------------
__global__ void k_pre(const float* __restrict__ skill_embed, const float* __restrict__ ans_embed,
                      const float* __restrict__ time_embed,
                      const float* __restrict__ W_sf, const float* __restrict__ b_sf,
                      const float* __restrict__ W_af, const float* __restrict__ b_af,
                      const float* __restrict__ W_ss, const float* __restrict__ b_ss,
                      const float* __restrict__ W_as, const float* __restrict__ b_as,
                      const float* __restrict__ W_o1, const float* __restrict__ b_o1) {
    __shared__ float s_src[DQ];
    int r = blockIdx.x;
    const float* src; const float* W; const float* bias; float* out;
    if (r < 200)       { src = time_embed + r * DQ;            W = W_sf + DQ * DQ;     bias = b_sf; out = g_pre_gap + r * DQ; }
    else if (r == 200) { src = time_embed + DQ;                W = W_af + DQ * DQ;     bias = b_af; out = g_caf; }
    else if (r < 501)  { int k = r - 201;  src = skill_embed + k * DQ; W = W_o1 + 2 * DQ * DQ; bias = b_o1; out = g_pre_o1 + k * DQ; }
    else if (r < 801)  { int k = r - 501;  src = skill_embed + k * DQ; W = W_as + DQ * DQ;     bias = b_as; out = g_pre_as_sk + k * DQ; }
    else if (r < 803)  { int a = r - 801;  src = ans_embed + a * DQ;   W = W_as + DQ * DQ;     bias = 0;    out = g_pre_as_an + a * DQ; }
    else if (r < 1103) { int k = r - 803;  src = skill_embed + k * DQ; W = W_ss + DQ * DQ;     bias = b_ss; out = g_pre_ss_sk + k * DQ; }
    else               { int a = r - 1103; src = ans_embed + a * DQ;   W = W_ss + DQ * DQ;     bias = 0;    out = g_pre_ss_an + a * DQ; }
    for (int i = threadIdx.x; i < DQ; i += blockDim.x) s_src[i] = src[i];
    __syncthreads();
    for (int j = threadIdx.x; j < DQ; j += blockDim.x) {
        float acc = bias ? bias[j] : 0.f;
        #pragma unroll 8
        for (int i = 0; i < DQ; i++) acc += s_src[i] * W[i * DQ + j];
        out[j] = acc;
    }
}

// ---------------- stage A: gates ----------------
// N-tiles 0..7  : f_sk path  (A = gathered history row, B = W_sf top half)
// N-tiles 8..15 : f_all path (A = all_state,           B = W_af top half)
__global__ void __launch_bounds__(256)
k_stageA(int s, const int* __restrict__ nsk,
         const float* __restrict__ W_sf, const float* __restrict__ W_af) {
    __shared__ const float* s_rowp[BM];
    __shared__ int s_gap[BM];
    __shared__ float As[2][BK][BM];
    __shared__ float Bs[2][BK][BN];

    const int nt = blockIdx.x;            // 0..15
    const int mt = blockIdx.y;            // 0..7
    const bool sf = (nt < 8);
    const int n0 = (nt & 7) * BN;
    const int m0 = mt * BM;
    const int tid = threadIdx.x;

    if (tid < BM) {
        int b = m0 + tid;
        if (sf) {
            int k = nsk[b * SQ + s];
            int t = g_lt[b * SKMAX + k];
            s_rowp[tid] = g_rows + ((size_t)b * SQ + t) * DQ;
            s_gap[tid] = s - t;
        } else {
            s_rowp[tid] = g_all + b * DQ;
        }
    }
    __syncthreads();

    const float* Wp = (sf ? W_sf : W_af) + n0;
    const int am = tid >> 2, akq = (tid & 3) * 4;
    const int bk = tid >> 4, bjq = (tid & 15) * 4;
    const int tx = tid & 15, ty = tid >> 4;
    const float* aptr = s_rowp[am] + akq;
    const float* bptr = Wp + bk * DQ + bjq;

    float acc[4][4] = {};

    // prologue load
    {
        float4 av = *(const float4*)(aptr);
        float4 bv = *(const float4*)(bptr);
        As[0][akq + 0][am] = av.x; As[0][akq + 1][am] = av.y;
        As[0][akq + 2][am] = av.z; As[0][akq + 3][am] = av.w;
        *(float4*)&Bs[0][bk][bjq] = bv;
    }
    __syncthreads();

    const int NK = DQ / BK;  // 32
    for (int kc = 0; kc < NK; kc++) {
        const int cur = kc & 1;
        float4 nav, nbv;
        const bool more = (kc + 1 < NK);
        if (more) {
            int k0 = (kc + 1) * BK;
            nav = *(const float4*)(aptr + k0);
            nbv = *(const float4*)(bptr + (size_t)k0 * DQ);
        }
        #pragma unroll
        for (int kk = 0; kk < BK; kk++) {
            float4 a4 = *(const float4*)&As[cur][kk][ty * 4];
            float4 b4 = *(const float4*)&Bs[cur][kk][tx * 4];
            float a[4] = {a4.x, a4.y, a4.z, a4.w};
            float bb[4] = {b4.x, b4.y, b4.z, b4.w};
            #pragma unroll
            for (int i = 0; i < 4; i++)
                #pragma unroll
                for (int j = 0; j < 4; j++) acc[i][j] += a[i] * bb[j];
        }
        if (more) {
            int nx = cur ^ 1;
            As[nx][akq + 0][am] = nav.x; As[nx][akq + 1][am] = nav.y;
            As[nx][akq + 2][am] = nav.z; As[nx][akq + 3][am] = nav.w;
            *(float4*)&Bs[nx][bk][bjq] = nbv;
        }
        __syncthreads();
    }

    float* outp = sf ? g_lsk : g_lall;
    #pragma unroll
    for (int i = 0; i < 4; i++) {
        int m = ty * 4 + i;
        int b = m0 + m;
        const float* xr = s_rowp[m];
        const float* prep = sf ? (g_pre_gap + s_gap[m] * DQ) : g_caf;
        #pragma unroll
        for (int j = 0; j < 4; j++) {
            int col = n0 + tx * 4 + j;
            float f = sigf(acc[i][j] + prep[col]);
            outp[b * DQ + col] = xr[col] * f;
        }
    }
}

// ---------------- stage B: hidden + state updates ----------------
// N-tiles 0..7  : h = relu([lall|lsk] @ W_o1[0:2d] + pre_o1[skill])          (K=1024)
// N-tiles 8..15 : new_all = lall + tanh(lall @ W_as_top + pre_as[...])       (K=512)
// N-tiles 16..23: new_sk  = lsk  + tanh(lsk  @ W_ss_top + pre_ss[...])       (K=512)
__global__ void __launch_bounds__(256)
k_stageB(int s, const int* __restrict__ nsk, const int* __restrict__ nans,
         const float* __restrict__ W_o1, const float* __restrict__ W_as,
         const float* __restrict__ W_ss) {
    __shared__ float As[2][BK][BM];
    __shared__ float Bs[2][BK][BN];

    const int nt = blockIdx.x;            // 0..23
    const int mt = blockIdx.y;            // 0..7
    const int region = nt >> 3;           // 0,1,2
    const int n0 = (nt & 7) * BN;
    const int m0 = mt * BM;
    const int tid = threadIdx.x;
    const int am = tid >> 2, akq = (tid & 3) * 4;
    const int bk = tid >> 4, bjq = (tid & 15) * 4;
    const int tx = tid & 15, ty = tid >> 4;

    const float* Wbase = (region == 0) ? W_o1 : (region == 1) ? W_as : W_ss;
    const float* bptr = Wbase + n0 + bk * DQ + bjq;
    const int KTOT = (region == 0) ? 2 * DQ : DQ;
    const int NK = KTOT / BK;
    const float* Abase0 = (region == 2) ? g_lsk : g_lall;

    auto aSrc = [&](int k0) -> const float* {
        const float* base = Abase0;
        int kk = k0;
        if (region == 0 && k0 >= DQ) { base = g_lsk; kk = k0 - DQ; }
        return base + (size_t)(m0 + am) * DQ + kk + akq;
    };

    float acc[4][4] = {};
    {
        float4 av = *(const float4*)aSrc(0);
        float4 bv = *(const float4*)(bptr);
        As[0][akq + 0][am] = av.x; As[0][akq + 1][am] = av.y;
        As[0][akq + 2][am] = av.z; As[0][akq + 3][am] = av.w;
        *(float4*)&Bs[0][bk][bjq] = bv;
    }
    __syncthreads();

    for (int kc = 0; kc < NK; kc++) {
        const int cur = kc & 1;
        float4 nav, nbv;
        const bool more = (kc + 1 < NK);
        if (more) {
            int k0 = (kc + 1) * BK;
            nav = *(const float4*)aSrc(k0);
            nbv = *(const float4*)(bptr + (size_t)k0 * DQ);
        }
        #pragma unroll
        for (int kk = 0; kk < BK; kk++) {
            float4 a4 = *(const float4*)&As[cur][kk][ty * 4];
            float4 b4 = *(const float4*)&Bs[cur][kk][tx * 4];
            float a[4] = {a4.x, a4.y, a4.z, a4.w};
            float bb[4] = {b4.x, b4.y, b4.z, b4.w};
            #pragma unroll
            for (int i = 0; i < 4; i++)
                #pragma unroll
                for (int j = 0; j < 4; j++) acc[i][j] += a[i] * bb[j];
        }
        if (more) {
            int nx = cur ^ 1;
            As[nx][akq + 0][am] = nav.x; As[nx][akq + 1][am] = nav.y;
            As[nx][akq + 2][am] = nav.z; As[nx][akq + 3][am] = nav.w;
            *(float4*)&Bs[nx][bk][bjq] = nbv;
        }
        __syncthreads();
    }

    #pragma unroll
    for (int i = 0; i < 4; i++) {
        int b = m0 + ty * 4 + i;
        int ks = nsk[b * SQ + s];
        #pragma unroll
        for (int j = 0; j < 4; j++) {
            int col = n0 + tx * 4 + j;
            float z = acc[i][j];
            if (region == 0) {
                z += g_pre_o1[ks * DQ + col];
                g_h[b * DQ + col] = fmaxf(z, 0.f);
            } else if (region == 1) {
                int a = nans[b * SQ + s];
                z += g_pre_as_sk[ks * DQ + col] + g_pre_as_an[a * DQ + col];
                g_all[b * DQ + col] = g_lall[b * DQ + col] + tanhf(z);
            } else {
                int a = nans[b * SQ + s];
                z += g_pre_ss_sk[ks * DQ + col] + g_pre_ss_an[a * DQ + col];
                g_rows[((size_t)b * SQ + s) * DQ + col] = g_lsk[b * DQ + col] + tanhf(z);
            }
        }
    }
}

// ---------------- stage C: output prob + last_time update ----------------
__global__ void k_stageC(int s, const int* __restrict__ nsk,
                         const float* __restrict__ W_o2, const float* __restrict__ b_o2,
                         float* __restrict__ P) {
    int warp = (blockIdx.x * blockDim.x + threadIdx.x) >> 5;  // 0..127
    int lane = threadIdx.x & 31;
    for (int b = warp; b < BQ; b += 128) {
        float acc = 0.f;
        for (int j = lane; j < DQ; j += 32) acc += g_h[b * DQ + j] * W_o2[j];
        #pragma unroll
        for (int off = 16; off; off >>= 1) acc += __shfl_xor_sync(0xffffffffu, acc, off);
        if (lane == 0) {
            P[b * SQ + s] = sigf(acc + b_o2[0]);
            g_lt[b * SKMAX + nsk[b * SQ + s]] = s;
        }
    }
}

// ---------------- launch ----------------
extern "C" void kernel_launch(void* const* d_in, const int* in_sizes, int n_in,
                              void* d_out, int out_size) {
    const int*   nsk          = (const int*)d_in[4];
    const int*   nans         = (const int*)d_in[5];
    const float* skill_embed  = (const float*)d_in[6];
    const float* ans_embed    = (const float*)d_in[7];
    const float* time_embed   = (const float*)d_in[8];
    const float* ls_state     = (const float*)d_in[9];
    const float* skill_state0 = (const float*)d_in[10];
    const float* W_sf = (const float*)d_in[11]; const float* b_sf = (const float*)d_in[12];
    const float* W_af = (const float*)d_in[13]; const float* b_af = (const float*)d_in[14];
    const float* W_ss = (const float*)d_in[15]; const float* b_ss = (const float*)d_in[16];
    const float* W_as = (const float*)d_in[17]; const float* b_as = (const float*)d_in[18];
    const float* W_o1 = (const float*)d_in[19]; const float* b_o1 = (const float*)d_in[20];
    const float* W_o2 = (const float*)d_in[21]; const float* b_o2 = (const float*)d_in[22];
    float* P = (float*)d_out;

    k_init_rows<<<dim3(SQ, BQ), 256>>>(skill_state0);
    k_init_state<<<BQ, 256>>>(ls_state);
    k_pre<<<1105, 256>>>(skill_embed, ans_embed, time_embed,
                         W_sf, b_sf, W_af, b_af, W_ss, b_ss, W_as, b_as, W_o1, b_o1);

    for (int s = 0; s < SQ; s++) {
        k_stageA<<<dim3(16, 8), 256>>>(s, nsk, W_sf, W_af);
        k_stageB<<<dim3(24, 8), 256>>>(s, nsk, nans, W_o1, W_as, W_ss);
        k_stageC<<<16, 256>>>(s, nsk, W_o2, b_o2, P);
    }
}